// round 7
// baseline (speedup 1.0000x reference)
#include <cuda_runtime.h>
#include <math.h>

#define NN 100000
#define NE 3200000
#define DF 128
#define HID 16
#define NC 2

// ---------------- scratch (no allocations allowed) ----------------
__device__ float  g_deg[NN];
__device__ float  g_dinv[NN];
__device__ float4 g_h1s[NN * 4];   // (x@W1) * dinv
__device__ float4 g_acc1[NN * 4];  // layer-1 aggregate (init = self-loop term)
__device__ float2 g_h2s[NN];       // (relu@W2) * dinv
__device__ float2 g_acc2[NN];      // layer-2 aggregate

// ---------------- kernels ----------------

__global__ void k_init_deg() {
    int i = blockIdx.x * blockDim.x + threadIdx.x;
    if (i < NN) g_deg[i] = 1.0f;  // self-loop
}

__global__ void k_deg(const int* __restrict__ dst) {
    int e = blockIdx.x * blockDim.x + threadIdx.x;
    if (e < NE) atomicAdd(&g_deg[dst[e]], 1.0f);  // RED, no return
}

__global__ void k_dinv() {
    int i = blockIdx.x * blockDim.x + threadIdx.x;
    if (i < NN) g_dinv[i] = rsqrtf(g_deg[i]);  // deg >= 1 always
}

// ---------------- GEMM1: 4 lanes/node, interleaved chunks + shfl reduce ----
// h1s[i] = acc1[i] = (x[i] @ W1) * dinv[i]
// Lane (n,c): loads x4[n*32 + k4*4 + c] (4 lanes of a node = 64 contiguous B,
// one 128B line; 8 lines per warp LDG instead of 32). Each lane accumulates
// all 16 outputs over its 32 k-values; 2-step shfl_xor over the c-lanes
// completes the dot products; lane c stores output chunk c.
__global__ void k_gemm1(const float* __restrict__ x, const float* __restrict__ W1) {
    __shared__ __align__(16) float W1s[DF * HID];   // 8 KB
    int tid = threadIdx.x;
    for (int i = tid; i < DF * HID; i += 256) W1s[i] = W1[i];
    __syncthreads();

    int lane = tid & 31;
    int warp = tid >> 5;
    int c = lane & 3;
    int node = blockIdx.x * 64 + warp * 8 + (lane >> 2);
    if (node >= NN) return;  // NN % 8 == 0: whole warp exits together

    const float4* xrow = (const float4*)(x + (size_t)node * DF);
    float acc[HID];
#pragma unroll
    for (int f = 0; f < HID; f++) acc[f] = 0.0f;

#pragma unroll
    for (int k4 = 0; k4 < 8; k4++) {
        float4 xv = __ldg(&xrow[k4 * 4 + c]);
        int kbase = k4 * 16 + c * 4;
#pragma unroll
        for (int j = 0; j < 4; j++) {
            float xs = (j == 0) ? xv.x : (j == 1) ? xv.y : (j == 2) ? xv.z : xv.w;
            const float4* wr = (const float4*)&W1s[(kbase + j) * HID];
#pragma unroll
            for (int q = 0; q < 4; q++) {
                float4 w = wr[q];
                acc[q * 4 + 0] = fmaf(xs, w.x, acc[q * 4 + 0]);
                acc[q * 4 + 1] = fmaf(xs, w.y, acc[q * 4 + 1]);
                acc[q * 4 + 2] = fmaf(xs, w.z, acc[q * 4 + 2]);
                acc[q * 4 + 3] = fmaf(xs, w.w, acc[q * 4 + 3]);
            }
        }
    }

    // Reduce across the 4 c-lanes of this node (lane bits [0:1]).
#pragma unroll
    for (int f = 0; f < HID; f++) {
        acc[f] += __shfl_xor_sync(0xffffffffu, acc[f], 1);
        acc[f] += __shfl_xor_sync(0xffffffffu, acc[f], 2);
    }

    float di = g_dinv[node];
    float4 o;
    o.x = acc[c * 4 + 0] * di;
    o.y = acc[c * 4 + 1] * di;
    o.z = acc[c * 4 + 2] * di;
    o.w = acc[c * 4 + 3] * di;
    g_h1s[node * 4 + c] = o;
    g_acc1[node * 4 + c] = o;   // self-loop init
}

// ---- layer-1 scatter: 4 threads/edge, one v4 RED each (R4 structure) ----
__global__ void k_scatter1(const int* __restrict__ src, const int* __restrict__ dst) {
    int t = blockIdx.x * blockDim.x + threadIdx.x;
    if (t >= NE * 4) return;
    int e = t >> 2;
    int c = t & 3;
    int s = src[e];
    int d = dst[e];
    float4 v = g_h1s[s * 4 + c];
    float4* p = &g_acc1[d * 4 + c];
    asm volatile("red.global.add.v4.f32 [%0], {%1, %2, %3, %4};"
                 :: "l"(p), "f"(v.x), "f"(v.y), "f"(v.z), "f"(v.w)
                 : "memory");
}

// Per node: finish layer1 (scale + bias + relu), apply W2, pre-scale for layer2.
__global__ void k_finish1(const float* __restrict__ b1, const float* __restrict__ W2) {
    int i = blockIdx.x * blockDim.x + threadIdx.x;
    if (i >= NN) return;
    float di = g_dinv[i];
    float z0 = 0.0f, z1 = 0.0f;
#pragma unroll
    for (int q = 0; q < 4; q++) {
        float4 a = g_acc1[i * 4 + q];
        float av[4] = {a.x, a.y, a.z, a.w};
#pragma unroll
        for (int j = 0; j < 4; j++) {
            int f = q * 4 + j;
            float v = fmaxf(fmaf(di, av[j], __ldg(&b1[f])), 0.0f);
            z0 = fmaf(v, __ldg(&W2[f * NC + 0]), z0);
            z1 = fmaf(v, __ldg(&W2[f * NC + 1]), z1);
        }
    }
    float2 h;
    h.x = z0 * di;
    h.y = z1 * di;
    g_h2s[i] = h;
    g_acc2[i] = h;  // self-loop init
}

// ---- layer-2 scatter: 1 thread/edge, 1 v2 RED (R4 structure) ----
__global__ void k_scatter2(const int* __restrict__ src, const int* __restrict__ dst) {
    int e = blockIdx.x * blockDim.x + threadIdx.x;
    if (e >= NE) return;
    int s = src[e];
    int d = dst[e];
    float2 v = g_h2s[s];
    float2* p = &g_acc2[d];
    asm volatile("red.global.add.v2.f32 [%0], {%1, %2};"
                 :: "l"(p), "f"(v.x), "f"(v.y) : "memory");
}

// Finish layer 2 + log_softmax (2 classes).
__global__ void k_final(const float* __restrict__ b2, float* __restrict__ out) {
    int i = blockIdx.x * blockDim.x + threadIdx.x;
    if (i >= NN) return;
    float di = g_dinv[i];
    float2 a = g_acc2[i];
    float z0 = fmaf(di, a.x, __ldg(&b2[0]));
    float z1 = fmaf(di, a.y, __ldg(&b2[1]));
    float m = fmaxf(z0, z1);
    float lse = m + logf(expf(z0 - m) + expf(z1 - m));
    float2 o;
    o.x = z0 - lse;
    o.y = z1 - lse;
    ((float2*)out)[i] = o;
}

// ---------------- launch ----------------

extern "C" void kernel_launch(void* const* d_in, const int* in_sizes, int n_in,
                              void* d_out, int out_size) {
    const float* x = 0; const float* W1 = 0; const float* b1 = 0;
    const float* W2 = 0; const float* b2 = 0; const int* ei = 0;
    for (int i = 0; i < n_in; i++) {
        long long s = in_sizes[i];
        if (s == (long long)NN * DF)      x  = (const float*)d_in[i];
        else if (s == DF * HID)           W1 = (const float*)d_in[i];
        else if (s == HID)                b1 = (const float*)d_in[i];
        else if (s == HID * NC)           W2 = (const float*)d_in[i];
        else if (s == NC)                 b2 = (const float*)d_in[i];
        else if (s == 2LL * NE)           ei = (const int*)d_in[i];
    }
    const int* src = ei;        // row 0
    const int* dst = ei + NE;   // row 1

    const int T = 256;
    const int NBn = (NN + T - 1) / T;
    const int NBe = (NE + T - 1) / T;

    k_init_deg<<<NBn, T>>>();
    k_deg<<<NBe, T>>>(dst);
    k_dinv<<<NBn, T>>>();
    k_gemm1<<<(NN + 63) / 64, 256>>>(x, W1);
    k_scatter1<<<(NE * 4 + T - 1) / T, T>>>(src, dst);
    k_finish1<<<NBn, T>>>(b1, W2);
    k_scatter2<<<NBe, T>>>(src, dst);
    k_final<<<NBn, T>>>(b2, (float*)d_out);
}

// round 8
// speedup vs baseline: 1.0006x; 1.0006x over previous
#include <cuda_runtime.h>
#include <math.h>

#define NN 100000
#define NE 3200000
#define DF 128
#define HID 16
#define NC 2

// ---------------- scratch (no allocations allowed) ----------------
__device__ float  g_deg[NN];
__device__ float  g_dinv[NN];
__device__ float4 g_h1s[NN * 4];   // (x@W1) * dinv
__device__ float4 g_acc1[NN * 4];  // layer-1 aggregate (init = self-loop term)
__device__ float2 g_h2s[NN];       // (relu@W2) * dinv
__device__ float2 g_acc2[NN];      // layer-2 aggregate

// ---------------- kernels ----------------

__global__ void k_init_deg() {
    int i = blockIdx.x * blockDim.x + threadIdx.x;
    if (i < NN) g_deg[i] = 1.0f;  // self-loop
}

__global__ void k_deg(const int* __restrict__ dst) {
    int e = blockIdx.x * blockDim.x + threadIdx.x;
    if (e < NE) atomicAdd(&g_deg[dst[e]], 1.0f);  // RED, no return
}

__global__ void k_dinv() {
    int i = blockIdx.x * blockDim.x + threadIdx.x;
    if (i < NN) g_dinv[i] = rsqrtf(g_deg[i]);  // deg >= 1 always
}

// ---------------- GEMM1: 4 lanes/node, interleaved chunks + shfl reduce ----
// h1s[i] = acc1[i] = (x[i] @ W1) * dinv[i]
// Lane (n,c): loads x4[n*32 + k4*4 + c] (4 lanes of a node = 64 contiguous B,
// one 128B line; 8 lines per warp LDG instead of 32). Each lane accumulates
// all 16 outputs over its 32 k-values; 2-step shfl_xor over the c-lanes
// completes the dot products; lane c stores output chunk c.
__global__ void k_gemm1(const float* __restrict__ x, const float* __restrict__ W1) {
    __shared__ __align__(16) float W1s[DF * HID];   // 8 KB
    int tid = threadIdx.x;
    for (int i = tid; i < DF * HID; i += 256) W1s[i] = W1[i];
    __syncthreads();

    int lane = tid & 31;
    int warp = tid >> 5;
    int c = lane & 3;
    int node = blockIdx.x * 64 + warp * 8 + (lane >> 2);
    if (node >= NN) return;  // NN % 8 == 0: whole warp exits together

    const float4* xrow = (const float4*)(x + (size_t)node * DF);
    float acc[HID];
#pragma unroll
    for (int f = 0; f < HID; f++) acc[f] = 0.0f;

#pragma unroll
    for (int k4 = 0; k4 < 8; k4++) {
        float4 xv = __ldg(&xrow[k4 * 4 + c]);
        int kbase = k4 * 16 + c * 4;
#pragma unroll
        for (int j = 0; j < 4; j++) {
            float xs = (j == 0) ? xv.x : (j == 1) ? xv.y : (j == 2) ? xv.z : xv.w;
            const float4* wr = (const float4*)&W1s[(kbase + j) * HID];
#pragma unroll
            for (int q = 0; q < 4; q++) {
                float4 w = wr[q];
                acc[q * 4 + 0] = fmaf(xs, w.x, acc[q * 4 + 0]);
                acc[q * 4 + 1] = fmaf(xs, w.y, acc[q * 4 + 1]);
                acc[q * 4 + 2] = fmaf(xs, w.z, acc[q * 4 + 2]);
                acc[q * 4 + 3] = fmaf(xs, w.w, acc[q * 4 + 3]);
            }
        }
    }

    // Reduce across the 4 c-lanes of this node (lane bits [0:1]).
#pragma unroll
    for (int f = 0; f < HID; f++) {
        acc[f] += __shfl_xor_sync(0xffffffffu, acc[f], 1);
        acc[f] += __shfl_xor_sync(0xffffffffu, acc[f], 2);
    }

    float di = g_dinv[node];
    float4 o;
    o.x = acc[c * 4 + 0] * di;
    o.y = acc[c * 4 + 1] * di;
    o.z = acc[c * 4 + 2] * di;
    o.w = acc[c * 4 + 3] * di;
    g_h1s[node * 4 + c] = o;
    g_acc1[node * 4 + c] = o;   // self-loop init
}

// ---- layer-1 scatter: 4 threads/edge, one v4 RED each (R4 structure) ----
__global__ void k_scatter1(const int* __restrict__ src, const int* __restrict__ dst) {
    int t = blockIdx.x * blockDim.x + threadIdx.x;
    if (t >= NE * 4) return;
    int e = t >> 2;
    int c = t & 3;
    int s = src[e];
    int d = dst[e];
    float4 v = g_h1s[s * 4 + c];
    float4* p = &g_acc1[d * 4 + c];
    asm volatile("red.global.add.v4.f32 [%0], {%1, %2, %3, %4};"
                 :: "l"(p), "f"(v.x), "f"(v.y), "f"(v.z), "f"(v.w)
                 : "memory");
}

// Per node: finish layer1 (scale + bias + relu), apply W2, pre-scale for layer2.
__global__ void k_finish1(const float* __restrict__ b1, const float* __restrict__ W2) {
    int i = blockIdx.x * blockDim.x + threadIdx.x;
    if (i >= NN) return;
    float di = g_dinv[i];
    float z0 = 0.0f, z1 = 0.0f;
#pragma unroll
    for (int q = 0; q < 4; q++) {
        float4 a = g_acc1[i * 4 + q];
        float av[4] = {a.x, a.y, a.z, a.w};
#pragma unroll
        for (int j = 0; j < 4; j++) {
            int f = q * 4 + j;
            float v = fmaxf(fmaf(di, av[j], __ldg(&b1[f])), 0.0f);
            z0 = fmaf(v, __ldg(&W2[f * NC + 0]), z0);
            z1 = fmaf(v, __ldg(&W2[f * NC + 1]), z1);
        }
    }
    float2 h;
    h.x = z0 * di;
    h.y = z1 * di;
    g_h2s[i] = h;
    g_acc2[i] = h;  // self-loop init
}

// ---- layer-2 scatter: 1 thread/edge, 1 v2 RED (R4 structure) ----
__global__ void k_scatter2(const int* __restrict__ src, const int* __restrict__ dst) {
    int e = blockIdx.x * blockDim.x + threadIdx.x;
    if (e >= NE) return;
    int s = src[e];
    int d = dst[e];
    float2 v = g_h2s[s];
    float2* p = &g_acc2[d];
    asm volatile("red.global.add.v2.f32 [%0], {%1, %2};"
                 :: "l"(p), "f"(v.x), "f"(v.y) : "memory");
}

// Finish layer 2 + log_softmax (2 classes).
__global__ void k_final(const float* __restrict__ b2, float* __restrict__ out) {
    int i = blockIdx.x * blockDim.x + threadIdx.x;
    if (i >= NN) return;
    float di = g_dinv[i];
    float2 a = g_acc2[i];
    float z0 = fmaf(di, a.x, __ldg(&b2[0]));
    float z1 = fmaf(di, a.y, __ldg(&b2[1]));
    float m = fmaxf(z0, z1);
    float lse = m + logf(expf(z0 - m) + expf(z1 - m));
    float2 o;
    o.x = z0 - lse;
    o.y = z1 - lse;
    ((float2*)out)[i] = o;
}

// ---------------- launch ----------------

extern "C" void kernel_launch(void* const* d_in, const int* in_sizes, int n_in,
                              void* d_out, int out_size) {
    const float* x = 0; const float* W1 = 0; const float* b1 = 0;
    const float* W2 = 0; const float* b2 = 0; const int* ei = 0;
    for (int i = 0; i < n_in; i++) {
        long long s = in_sizes[i];
        if (s == (long long)NN * DF)      x  = (const float*)d_in[i];
        else if (s == DF * HID)           W1 = (const float*)d_in[i];
        else if (s == HID)                b1 = (const float*)d_in[i];
        else if (s == HID * NC)           W2 = (const float*)d_in[i];
        else if (s == NC)                 b2 = (const float*)d_in[i];
        else if (s == 2LL * NE)           ei = (const int*)d_in[i];
    }
    const int* src = ei;        // row 0
    const int* dst = ei + NE;   // row 1

    const int T = 256;
    const int NBn = (NN + T - 1) / T;
    const int NBe = (NE + T - 1) / T;

    k_init_deg<<<NBn, T>>>();
    k_deg<<<NBe, T>>>(dst);
    k_dinv<<<NBn, T>>>();
    k_gemm1<<<(NN + 63) / 64, 256>>>(x, W1);
    k_scatter1<<<(NE * 4 + T - 1) / T, T>>>(src, dst);
    k_finish1<<<NBn, T>>>(b1, W2);
    k_scatter2<<<NBe, T>>>(src, dst);
    k_final<<<NBn, T>>>(b2, (float*)d_out);
}

// round 9
// speedup vs baseline: 1.4725x; 1.4717x over previous
#include <cuda_runtime.h>
#include <math.h>

#define NN 100000
#define NE 3200000
#define DF 128
#define HID 16
#define NC 2
#define GB 64               // nodes (and threads) per gemm1 block
#define XP 133              // XS row stride in floats: (133*n+k)%32=(5n+k)%32, 5 coprime 32

// ---------------- scratch (no allocations allowed) ----------------
__device__ float  g_deg[NN];
__device__ float  g_dinv[NN];
__device__ float4 g_h1s[NN * 4];   // (x@W1) * dinv
__device__ float4 g_acc1[NN * 4];  // layer-1 aggregate (init = self-loop term)
__device__ float2 g_h2s[NN];       // (relu@W2) * dinv
__device__ float2 g_acc2[NN];      // layer-2 aggregate

// ---------------- kernels ----------------

__global__ void k_init_deg() {
    int i = blockIdx.x * blockDim.x + threadIdx.x;
    if (i < NN) g_deg[i] = 1.0f;  // self-loop
}

__global__ void k_deg(const int* __restrict__ dst) {
    int e = blockIdx.x * blockDim.x + threadIdx.x;
    if (e < NE) atomicAdd(&g_deg[dst[e]], 1.0f);  // RED, no return
}

__global__ void k_dinv() {
    int i = blockIdx.x * blockDim.x + threadIdx.x;
    if (i < NN) g_dinv[i] = rsqrtf(g_deg[i]);  // deg >= 1 always
}

// ---------------- GEMM1: smem-staged, conflict-free ----------------
// 1 thread = 1 node (R4 compute structure). x tile staged coalesced into XS
// with row stride 133 floats so per-k scalar reads are bank-conflict-free
// across the warp. W reads are warp-uniform (broadcast).
__global__ void __launch_bounds__(GB) k_gemm1(const float* __restrict__ x,
                                              const float* __restrict__ W1) {
    __shared__ __align__(16) float W1s[DF * HID];  // 8 KB
    __shared__ __align__(16) float XS[GB * XP];    // 34.1 KB
    int tid = threadIdx.x;
    int base = blockIdx.x * GB;
    int nb = NN - base; if (nb > GB) nb = GB;

    for (int i = tid; i < DF * HID; i += GB) W1s[i] = W1[i];

    // Coalesced tile load: consecutive threads -> consecutive float4s.
    const float4* xg = (const float4*)(x + (size_t)base * DF);
    for (int i = tid; i < nb * 32; i += GB) {
        int n = i >> 5, m = i & 31;
        float4 v = xg[i];
        float* p = &XS[n * XP + m * 4];
        p[0] = v.x; p[1] = v.y; p[2] = v.z; p[3] = v.w;
    }
    __syncthreads();

    int n = tid;
    if (n >= nb) return;
    int node = base + n;

    float acc[HID];
#pragma unroll
    for (int f = 0; f < HID; f++) acc[f] = 0.0f;

    const float* xr = &XS[n * XP];
#pragma unroll 8
    for (int k = 0; k < DF; k++) {
        float xs = xr[k];                       // conflict-free scalar LDS
        const float4* wr = (const float4*)&W1s[k * HID];  // warp-uniform: broadcast
#pragma unroll
        for (int q = 0; q < 4; q++) {
            float4 w = wr[q];
            acc[q * 4 + 0] = fmaf(xs, w.x, acc[q * 4 + 0]);
            acc[q * 4 + 1] = fmaf(xs, w.y, acc[q * 4 + 1]);
            acc[q * 4 + 2] = fmaf(xs, w.z, acc[q * 4 + 2]);
            acc[q * 4 + 3] = fmaf(xs, w.w, acc[q * 4 + 3]);
        }
    }

    float di = g_dinv[node];
#pragma unroll
    for (int q = 0; q < 4; q++) {
        float4 v;
        v.x = acc[q * 4 + 0] * di;
        v.y = acc[q * 4 + 1] * di;
        v.z = acc[q * 4 + 2] * di;
        v.w = acc[q * 4 + 3] * di;
        g_h1s[node * 4 + q] = v;
        g_acc1[node * 4 + q] = v;   // self-loop init
    }
}

// ---- layer-1 scatter: 4 threads/edge, one v4 RED each (R4, proven) ----
__global__ void k_scatter1(const int* __restrict__ src, const int* __restrict__ dst) {
    int t = blockIdx.x * blockDim.x + threadIdx.x;
    if (t >= NE * 4) return;
    int e = t >> 2;
    int c = t & 3;
    int s = src[e];
    int d = dst[e];
    float4 v = g_h1s[s * 4 + c];
    float4* p = &g_acc1[d * 4 + c];
    asm volatile("red.global.add.v4.f32 [%0], {%1, %2, %3, %4};"
                 :: "l"(p), "f"(v.x), "f"(v.y), "f"(v.z), "f"(v.w)
                 : "memory");
}

// Per node: finish layer1 (scale + bias + relu), apply W2, pre-scale for layer2.
__global__ void k_finish1(const float* __restrict__ b1, const float* __restrict__ W2) {
    int i = blockIdx.x * blockDim.x + threadIdx.x;
    if (i >= NN) return;
    float di = g_dinv[i];
    float z0 = 0.0f, z1 = 0.0f;
#pragma unroll
    for (int q = 0; q < 4; q++) {
        float4 a = g_acc1[i * 4 + q];
        float av[4] = {a.x, a.y, a.z, a.w};
#pragma unroll
        for (int j = 0; j < 4; j++) {
            int f = q * 4 + j;
            float v = fmaxf(fmaf(di, av[j], __ldg(&b1[f])), 0.0f);
            z0 = fmaf(v, __ldg(&W2[f * NC + 0]), z0);
            z1 = fmaf(v, __ldg(&W2[f * NC + 1]), z1);
        }
    }
    float2 h;
    h.x = z0 * di;
    h.y = z1 * di;
    g_h2s[i] = h;
    g_acc2[i] = h;  // self-loop init
}

// ---- layer-2 scatter: 1 thread/edge, 1 v2 RED (R4, proven) ----
__global__ void k_scatter2(const int* __restrict__ src, const int* __restrict__ dst) {
    int e = blockIdx.x * blockDim.x + threadIdx.x;
    if (e >= NE) return;
    int s = src[e];
    int d = dst[e];
    float2 v = g_h2s[s];
    float2* p = &g_acc2[d];
    asm volatile("red.global.add.v2.f32 [%0], {%1, %2};"
                 :: "l"(p), "f"(v.x), "f"(v.y) : "memory");
}

// Finish layer 2 + log_softmax (2 classes).
__global__ void k_final(const float* __restrict__ b2, float* __restrict__ out) {
    int i = blockIdx.x * blockDim.x + threadIdx.x;
    if (i >= NN) return;
    float di = g_dinv[i];
    float2 a = g_acc2[i];
    float z0 = fmaf(di, a.x, __ldg(&b2[0]));
    float z1 = fmaf(di, a.y, __ldg(&b2[1]));
    float m = fmaxf(z0, z1);
    float lse = m + logf(expf(z0 - m) + expf(z1 - m));
    float2 o;
    o.x = z0 - lse;
    o.y = z1 - lse;
    ((float2*)out)[i] = o;
}

// ---------------- launch ----------------

extern "C" void kernel_launch(void* const* d_in, const int* in_sizes, int n_in,
                              void* d_out, int out_size) {
    const float* x = 0; const float* W1 = 0; const float* b1 = 0;
    const float* W2 = 0; const float* b2 = 0; const int* ei = 0;
    for (int i = 0; i < n_in; i++) {
        long long s = in_sizes[i];
        if (s == (long long)NN * DF)      x  = (const float*)d_in[i];
        else if (s == DF * HID)           W1 = (const float*)d_in[i];
        else if (s == HID)                b1 = (const float*)d_in[i];
        else if (s == HID * NC)           W2 = (const float*)d_in[i];
        else if (s == NC)                 b2 = (const float*)d_in[i];
        else if (s == 2LL * NE)           ei = (const int*)d_in[i];
    }
    const int* src = ei;        // row 0
    const int* dst = ei + NE;   // row 1

    const int T = 256;
    const int NBn = (NN + T - 1) / T;
    const int NBe = (NE + T - 1) / T;

    k_init_deg<<<NBn, T>>>();
    k_deg<<<NBe, T>>>(dst);
    k_dinv<<<NBn, T>>>();
    k_gemm1<<<(NN + GB - 1) / GB, GB>>>(x, W1);
    k_scatter1<<<(NE * 4 + T - 1) / T, T>>>(src, dst);
    k_finish1<<<NBn, T>>>(b1, W2);
    k_scatter2<<<NBe, T>>>(src, dst);
    k_final<<<NBn, T>>>(b2, (float*)d_out);
}

// round 10
// speedup vs baseline: 1.4925x; 1.0136x over previous
#include <cuda_runtime.h>
#include <math.h>

#define NN 100000
#define NE 3200000
#define DF 128
#define HID 16
#define NC 2
#define GB 256              // nodes (and threads) per gemm1 block
#define XP 33               // XS row stride (odd): compute bank = (n+k)%32, conflict-free
#define KC 32               // k-chunk size

// ---------------- scratch (no allocations allowed) ----------------
__device__ float  g_deg[NN];
__device__ float  g_dinv[NN];
__device__ float4 g_h1s[NN * 4];   // (x@W1) * dinv
__device__ float4 g_acc1[NN * 4];  // layer-1 aggregate (init = self-loop term)
__device__ float2 g_h2s[NN];       // (relu@W2) * dinv
__device__ float2 g_acc2[NN];      // layer-2 aggregate

// ---------------- kernels ----------------

__global__ void k_init_deg() {
    int i = blockIdx.x * blockDim.x + threadIdx.x;
    if (i < NN) g_deg[i] = 1.0f;  // self-loop
}

__global__ void k_deg(const int* __restrict__ dst) {
    int e = blockIdx.x * blockDim.x + threadIdx.x;
    if (e < NE) atomicAdd(&g_deg[dst[e]], 1.0f);  // RED, no return
}

__global__ void k_dinv() {
    int i = blockIdx.x * blockDim.x + threadIdx.x;
    if (i < NN) g_dinv[i] = rsqrtf(g_deg[i]);  // deg >= 1 always
}

// ---------------- GEMM1: k-chunked smem staging, conflict-free, high-occ ----
// 256 threads = 256 nodes per block; x staged in 4 chunks of 32 k-values.
// XS stride 33 (odd): store bank (n+4*j4+t)%32 and compute bank (n+k)%32 are
// both conflict-free. W reads are warp-uniform (broadcast). 41.8 KB smem ->
// ~5 blocks/SM = 40 warps (vs 9 in R9).
__global__ void __launch_bounds__(GB) k_gemm1(const float* __restrict__ x,
                                              const float* __restrict__ W1) {
    __shared__ __align__(16) float W1s[DF * HID];  // 8 KB
    __shared__ float XS[GB * XP];                  // 33.8 KB
    int tid = threadIdx.x;
    int base = blockIdx.x * GB;
    int nb = NN - base; if (nb > GB) nb = GB;

    for (int i = tid; i < DF * HID; i += GB) W1s[i] = W1[i];

    float acc[HID];
#pragma unroll
    for (int f = 0; f < HID; f++) acc[f] = 0.0f;

    for (int ch = 0; ch < DF / KC; ch++) {
        __syncthreads();  // previous chunk fully consumed
        // Load chunk: node n, k in [ch*KC, ch*KC+KC). Lanes cover 4x128B lines.
        for (int i = tid; i < nb * (KC / 4); i += GB) {
            int n = i >> 3, j4 = i & 7;
            float4 v = *(const float4*)(x + (size_t)(base + n) * DF + ch * KC + j4 * 4);
            float* p = &XS[n * XP + j4 * 4];
            p[0] = v.x; p[1] = v.y; p[2] = v.z; p[3] = v.w;  // scalar STS: keeps stride odd
        }
        __syncthreads();

        if (tid < nb) {
            const float* xr = &XS[tid * XP];
#pragma unroll
            for (int kk = 0; kk < KC; kk++) {
                float xs = xr[kk];  // bank (n+k)%32: conflict-free
                const float4* wr = (const float4*)&W1s[(ch * KC + kk) * HID];  // uniform
#pragma unroll
                for (int q = 0; q < 4; q++) {
                    float4 w = wr[q];
                    acc[q * 4 + 0] = fmaf(xs, w.x, acc[q * 4 + 0]);
                    acc[q * 4 + 1] = fmaf(xs, w.y, acc[q * 4 + 1]);
                    acc[q * 4 + 2] = fmaf(xs, w.z, acc[q * 4 + 2]);
                    acc[q * 4 + 3] = fmaf(xs, w.w, acc[q * 4 + 3]);
                }
            }
        }
    }

    if (tid >= nb) return;
    int node = base + tid;
    float di = g_dinv[node];
#pragma unroll
    for (int q = 0; q < 4; q++) {
        float4 v;
        v.x = acc[q * 4 + 0] * di;
        v.y = acc[q * 4 + 1] * di;
        v.z = acc[q * 4 + 2] * di;
        v.w = acc[q * 4 + 3] * di;
        g_h1s[node * 4 + q] = v;
        g_acc1[node * 4 + q] = v;   // self-loop init
    }
}

// ---- layer-1 scatter: 4 threads/edge, one v4 RED each (R4, proven) ----
__global__ void k_scatter1(const int* __restrict__ src, const int* __restrict__ dst) {
    int t = blockIdx.x * blockDim.x + threadIdx.x;
    if (t >= NE * 4) return;
    int e = t >> 2;
    int c = t & 3;
    int s = src[e];
    int d = dst[e];
    float4 v = g_h1s[s * 4 + c];
    float4* p = &g_acc1[d * 4 + c];
    asm volatile("red.global.add.v4.f32 [%0], {%1, %2, %3, %4};"
                 :: "l"(p), "f"(v.x), "f"(v.y), "f"(v.z), "f"(v.w)
                 : "memory");
}

// Per node: finish layer1 (scale + bias + relu), apply W2, pre-scale for layer2.
__global__ void k_finish1(const float* __restrict__ b1, const float* __restrict__ W2) {
    int i = blockIdx.x * blockDim.x + threadIdx.x;
    if (i >= NN) return;
    float di = g_dinv[i];
    float z0 = 0.0f, z1 = 0.0f;
#pragma unroll
    for (int q = 0; q < 4; q++) {
        float4 a = g_acc1[i * 4 + q];
        float av[4] = {a.x, a.y, a.z, a.w};
#pragma unroll
        for (int j = 0; j < 4; j++) {
            int f = q * 4 + j;
            float v = fmaxf(fmaf(di, av[j], __ldg(&b1[f])), 0.0f);
            z0 = fmaf(v, __ldg(&W2[f * NC + 0]), z0);
            z1 = fmaf(v, __ldg(&W2[f * NC + 1]), z1);
        }
    }
    float2 h;
    h.x = z0 * di;
    h.y = z1 * di;
    g_h2s[i] = h;
    g_acc2[i] = h;  // self-loop init
}

// ---- layer-2 scatter: 1 thread/edge, 1 v2 RED (R4, proven) ----
__global__ void k_scatter2(const int* __restrict__ src, const int* __restrict__ dst) {
    int e = blockIdx.x * blockDim.x + threadIdx.x;
    if (e >= NE) return;
    int s = src[e];
    int d = dst[e];
    float2 v = g_h2s[s];
    float2* p = &g_acc2[d];
    asm volatile("red.global.add.v2.f32 [%0], {%1, %2};"
                 :: "l"(p), "f"(v.x), "f"(v.y) : "memory");
}

// Finish layer 2 + log_softmax (2 classes).
__global__ void k_final(const float* __restrict__ b2, float* __restrict__ out) {
    int i = blockIdx.x * blockDim.x + threadIdx.x;
    if (i >= NN) return;
    float di = g_dinv[i];
    float2 a = g_acc2[i];
    float z0 = fmaf(di, a.x, __ldg(&b2[0]));
    float z1 = fmaf(di, a.y, __ldg(&b2[1]));
    float m = fmaxf(z0, z1);
    float lse = m + logf(expf(z0 - m) + expf(z1 - m));
    float2 o;
    o.x = z0 - lse;
    o.y = z1 - lse;
    ((float2*)out)[i] = o;
}

// ---------------- launch ----------------

extern "C" void kernel_launch(void* const* d_in, const int* in_sizes, int n_in,
                              void* d_out, int out_size) {
    const float* x = 0; const float* W1 = 0; const float* b1 = 0;
    const float* W2 = 0; const float* b2 = 0; const int* ei = 0;
    for (int i = 0; i < n_in; i++) {
        long long s = in_sizes[i];
        if (s == (long long)NN * DF)      x  = (const float*)d_in[i];
        else if (s == DF * HID)           W1 = (const float*)d_in[i];
        else if (s == HID)                b1 = (const float*)d_in[i];
        else if (s == HID * NC)           W2 = (const float*)d_in[i];
        else if (s == NC)                 b2 = (const float*)d_in[i];
        else if (s == 2LL * NE)           ei = (const int*)d_in[i];
    }
    const int* src = ei;        // row 0
    const int* dst = ei + NE;   // row 1

    const int T = 256;
    const int NBn = (NN + T - 1) / T;
    const int NBe = (NE + T - 1) / T;

    k_init_deg<<<NBn, T>>>();
    k_deg<<<NBe, T>>>(dst);
    k_dinv<<<NBn, T>>>();
    k_gemm1<<<(NN + GB - 1) / GB, GB>>>(x, W1);
    k_scatter1<<<(NE * 4 + T - 1) / T, T>>>(src, dst);
    k_finish1<<<NBn, T>>>(b1, W2);
    k_scatter2<<<NBe, T>>>(src, dst);
    k_final<<<NBn, T>>>(b2, (float*)d_out);
}